// round 1
// baseline (speedup 1.0000x reference)
#include <cuda_runtime.h>
#include <math.h>

#define NTHREADS 256
#define TOPK_K   200
#define PARTS    32
#define EQ_CAP   256

// Replicates the reference's per-point bin computation for rel = q_j - q_0,
// then bumps the shared histogram.
__device__ __forceinline__ void process_point(
    int i, const float* __restrict__ fp,
    float q0x, float q0y, float q0z,
    unsigned int* counts)
{
    const float TWO_PI_F = 6.28318530717958647692f;  // f32(2*pi)
    const float PI_F     = 3.14159265358979323846f;  // f32(pi)

    float rx = __fsub_rn(fp[3 * i + 0], q0x);
    float ry = __fsub_rn(fp[3 * i + 1], q0y);
    float rz = __fsub_rn(fp[3 * i + 2], q0z);

    float axy = fmodf(atan2f(ry, rx) + TWO_PI_F, TWO_PI_F);
    float azy = fmodf(atan2f(ry, rz) + TWO_PI_F, PI_F);
    int xyb = (int)floorf(axy / (TWO_PI_F * 0.25f));  // == f32(2pi/4) exactly
    int zyb = (int)floorf(azy / (PI_F * 0.25f));      // == f32(pi/4) exactly

    float d2 = __fadd_rn(__fadd_rn(__fmul_rn(rx, rx), __fmul_rn(ry, ry)),
                         __fmul_rn(rz, rz));
    float D = sqrtf(__fadd_rn(d2, 1e-7f));
    int dist = (D >= 4.0f) ? 1 : ((D >= 1.0f) ? 0 : -1);

    if (dist >= 0 && xyb >= 0 && zyb >= 0) {
        int bin = dist * (4 * 4) + xyb * 4 + zyb;
        if (bin >= 0 && bin < PARTS) atomicAdd(&counts[bin], 1u);
    }
}

__global__ __launch_bounds__(NTHREADS)
void scp_topk_bins_kernel(const float* __restrict__ vp,
                          const float* __restrict__ fp,
                          float* __restrict__ out,
                          int n_fp)
{
    // Dynamic shared: one uint32 key (float bits of d^2, d^2 >= 0 so order-preserving)
    // per fusion point.
    extern __shared__ unsigned int keys[];

    __shared__ unsigned int hist[256];
    __shared__ unsigned int eq_idx[EQ_CAP];
    __shared__ unsigned int counts[PARTS];
    __shared__ unsigned long long minpack;
    __shared__ unsigned int s_eq_count;
    __shared__ unsigned int s_prefix;
    __shared__ int s_need;

    const int b = blockIdx.x;
    const int t = threadIdx.x;

    const float vx = vp[3 * b + 0];
    const float vy = vp[3 * b + 1];
    const float vz = vp[3 * b + 2];

    if (t < PARTS) counts[t] = 0;
    if (t == 0) { minpack = ~0ull; s_eq_count = 0; }
    for (int i = t; i < 256; i += NTHREADS) hist[i] = 0;
    __syncthreads();

    // --- Pass 1: distances -> keys in smem; fold radix pass 0 histogram; track argmin.
    unsigned long long lmin = ~0ull;
    for (int i = t; i < n_fp; i += NTHREADS) {
        float fx = fp[3 * i + 0];
        float fy = fp[3 * i + 1];
        float fz = fp[3 * i + 2];
        float dx = __fsub_rn(vx, fx);
        float dy = __fsub_rn(vy, fy);
        float dz = __fsub_rn(vz, fz);
        float d2 = __fadd_rn(__fadd_rn(__fmul_rn(dx, dx), __fmul_rn(dy, dy)),
                             __fmul_rn(dz, dz));
        unsigned int k = __float_as_uint(d2);
        keys[i] = k;
        atomicAdd(&hist[k >> 24], 1u);
        unsigned long long pk =
            ((unsigned long long)k << 32) | (unsigned long long)(unsigned int)i;
        if (pk < lmin) lmin = pk;
    }
    atomicMin(&minpack, lmin);
    __syncthreads();

    // --- Exact 200th-smallest via MSB radix select (8 bits x 4 passes).
    unsigned int prefix = 0;
    int need = TOPK_K;
    for (int pass = 0; pass < 4; ++pass) {
        const int shift = 24 - 8 * pass;
        if (t == 0) {
            int c = 0, d = 0;
            for (; d < 256; ++d) {
                int h = (int)hist[d];
                if (c + h >= need) break;
                c += h;
            }
            s_prefix = prefix | ((unsigned int)d << shift);
            s_need = need - c;
        }
        __syncthreads();
        prefix = s_prefix;
        need = s_need;
        if (pass < 3) {
            for (int i = t; i < 256; i += NTHREADS) hist[i] = 0;
            __syncthreads();
            const unsigned int mask = 0xFFFFFFFFu << shift;  // fixed high digits
            const int nshift = shift - 8;
            for (int i = t; i < n_fp; i += NTHREADS) {
                unsigned int k = keys[i];
                if ((k & mask) == prefix)
                    atomicAdd(&hist[(k >> nshift) & 255u], 1u);
            }
            __syncthreads();
        }
    }
    const unsigned int V = prefix;  // key of the 200th smallest
    // `need` now == number of keys equal to V to take (lowest indices first),
    // matching jax.lax.top_k tie semantics.

    // --- Anchor = nearest fusion point (lowest index on key ties).
    const unsigned int amin = (unsigned int)(minpack & 0xFFFFFFFFull);
    const float q0x = fp[3 * amin + 0];
    const float q0y = fp[3 * amin + 1];
    const float q0z = fp[3 * amin + 2];

    // --- Selection + histogram.
    for (int i = t; i < n_fp; i += NTHREADS) {
        unsigned int k = keys[i];
        if (k < V) {
            process_point(i, fp, q0x, q0y, q0z, counts);
        } else if (k == V) {
            unsigned int p = atomicAdd(&s_eq_count, 1u);
            if (p < EQ_CAP) eq_idx[p] = (unsigned int)i;
        }
    }
    __syncthreads();

    // Ties at the threshold: take lowest indices first.
    unsigned int ne = min(s_eq_count, (unsigned int)EQ_CAP);
    for (unsigned int j = t; j < ne; j += NTHREADS) {
        unsigned int my = eq_idx[j];
        int rank = 0;
        for (unsigned int l = 0; l < ne; ++l) rank += (eq_idx[l] < my) ? 1 : 0;
        if (rank < need) process_point((int)my, fp, q0x, q0y, q0z, counts);
    }
    __syncthreads();

    // --- counts+1 -> L2-normalize*4 -> softmax, warp 0 only.
    if (t < 32) {
        float c = (float)counts[t] + 1.0f;
        float ss = c * c;
        #pragma unroll
        for (int o = 16; o > 0; o >>= 1) ss += __shfl_xor_sync(0xFFFFFFFFu, ss, o);
        float pip = (c / sqrtf(ss)) * 4.0f;
        float m = pip;
        #pragma unroll
        for (int o = 16; o > 0; o >>= 1)
            m = fmaxf(m, __shfl_xor_sync(0xFFFFFFFFu, m, o));
        float e = expf(pip - m);
        float se = e;
        #pragma unroll
        for (int o = 16; o > 0; o >>= 1) se += __shfl_xor_sync(0xFFFFFFFFu, se, o);
        out[b * PARTS + t] = e / se;
    }
}

extern "C" void kernel_launch(void* const* d_in, const int* in_sizes, int n_in,
                              void* d_out, int out_size)
{
    const float* vp = (const float*)d_in[0];   // sampled_vehicle_points (n_vp, 3)
    const float* fp = (const float*)d_in[1];   // fusion_point          (n_fp, 3)
    float* out = (float*)d_out;                // (n_vp, 32)

    const int n_vp = in_sizes[0] / 3;
    const int n_fp = in_sizes[1] / 3;

    const size_t smem = (size_t)n_fp * sizeof(unsigned int);  // 80 KB for n_fp=20000
    cudaFuncSetAttribute(scp_topk_bins_kernel,
                         cudaFuncAttributeMaxDynamicSharedMemorySize, (int)smem);

    scp_topk_bins_kernel<<<n_vp, NTHREADS, smem>>>(vp, fp, out, n_fp);
}

// round 3
// speedup vs baseline: 1.4398x; 1.4398x over previous
#include <cuda_runtime.h>
#include <math.h>

#define NTHREADS 256
#define TOPK_K   200
#define PARTS    32
#define CAND_CAP 4096

// ---------------------------------------------------------------------------
// d^2 with a fixed, non-FMA operation order so pass A and pass B produce
// bit-identical keys (and match XLA's unfused sum-of-squares).
__device__ __forceinline__ unsigned int compute_key(
    float vx, float vy, float vz, const float* __restrict__ fp, int i)
{
    float dx = __fsub_rn(vx, fp[3 * i + 0]);
    float dy = __fsub_rn(vy, fp[3 * i + 1]);
    float dz = __fsub_rn(vz, fp[3 * i + 2]);
    float d2 = __fadd_rn(__fadd_rn(__fmul_rn(dx, dx), __fmul_rn(dy, dy)),
                         __fmul_rn(dz, dz));
    return __float_as_uint(d2);   // d2 >= 0, so uint order == float order
}

// Replicates the reference's per-point bin computation for rel = q_j - q_0.
__device__ __forceinline__ void process_point(
    int i, const float* __restrict__ fp,
    float q0x, float q0y, float q0z,
    unsigned int* counts)
{
    const float TWO_PI_F = 6.28318530717958647692f;
    const float PI_F     = 3.14159265358979323846f;

    float rx = __fsub_rn(fp[3 * i + 0], q0x);
    float ry = __fsub_rn(fp[3 * i + 1], q0y);
    float rz = __fsub_rn(fp[3 * i + 2], q0z);

    float axy = fmodf(atan2f(ry, rx) + TWO_PI_F, TWO_PI_F);
    float azy = fmodf(atan2f(ry, rz) + TWO_PI_F, PI_F);
    int xyb = (int)floorf(axy / (TWO_PI_F * 0.25f));
    int zyb = (int)floorf(azy / (PI_F * 0.25f));

    float d2 = __fadd_rn(__fadd_rn(__fmul_rn(rx, rx), __fmul_rn(ry, ry)),
                         __fmul_rn(rz, rz));
    float D = sqrtf(__fadd_rn(d2, 1e-7f));
    int dist = (D >= 4.0f) ? 1 : ((D >= 1.0f) ? 0 : -1);

    if (dist >= 0 && xyb >= 0 && zyb >= 0) {
        int bin = dist * 16 + xyb * 4 + zyb;
        if (bin >= 0 && bin < PARTS) atomicAdd(&counts[bin], 1u);
    }
}

// Parallel "find digit d where cumulative count reaches `need`" over a 256-bin
// histogram. Warp 0 only; result broadcast through shared.
__device__ __forceinline__ void find_digit(
    unsigned int* hist, int need, int t,
    unsigned int* s_digit, int* s_need)
{
    if (t < 32) {
        int base = t * 8;
        int s = 0;
        #pragma unroll
        for (int j = 0; j < 8; ++j) s += (int)hist[base + j];
        int cum = s;
        #pragma unroll
        for (int o = 1; o < 32; o <<= 1) {
            int v = __shfl_up_sync(0xFFFFFFFFu, cum, o);
            if (t >= o) cum += v;
        }
        unsigned int bal = __ballot_sync(0xFFFFFFFFu, cum >= need);
        int lane = __ffs(bal) - 1;
        if (t == lane) {
            int c = cum - s;   // exclusive prefix at this lane's first bin
            int d = base;
            while (c + (int)hist[d] < need) { c += (int)hist[d]; ++d; }
            *s_digit = (unsigned int)d;
            *s_need = need - c;
        }
    }
    __syncthreads();
}

__global__ __launch_bounds__(NTHREADS)
void scp_topk_bins_kernel(const float* __restrict__ vp,
                          const float* __restrict__ fp,
                          float* __restrict__ out,
                          int n_fp)
{
    __shared__ unsigned int hist[256];
    __shared__ unsigned long long cand[CAND_CAP];  // (key<<32)|idx
    __shared__ unsigned int counts[PARTS];
    __shared__ unsigned long long minpack;
    __shared__ unsigned int s_cand_count;
    __shared__ unsigned int s_digit;
    __shared__ int s_need;

    const int b = blockIdx.x;
    const int t = threadIdx.x;

    const float vx = vp[3 * b + 0];
    const float vy = vp[3 * b + 1];
    const float vz = vp[3 * b + 2];

    if (t < PARTS) counts[t] = 0;
    if (t == 0) { minpack = ~0ull; s_cand_count = 0; }
    hist[t] = 0;
    if (t < 256 - NTHREADS + 256) {}  // (NTHREADS==256 covers hist exactly)
    __syncthreads();

    const int niter = (n_fp + NTHREADS - 1) / NTHREADS;

    // ---- Pass A: digit-0 histogram (warp-aggregated) + packed argmin.
    unsigned long long lmin = ~0ull;
    for (int it = 0; it < niter; ++it) {
        int i = it * NTHREADS + t;
        bool valid = (i < n_fp);
        unsigned int active = __ballot_sync(0xFFFFFFFFu, valid);
        if (valid) {
            unsigned int k = compute_key(vx, vy, vz, fp, i);
            unsigned int d = k >> 24;
            unsigned int peers = __match_any_sync(active, d);
            int leader = __ffs(peers) - 1;
            if ((int)(t & 31) == leader)
                atomicAdd(&hist[d], (unsigned int)__popc(peers));
            unsigned long long pk =
                ((unsigned long long)k << 32) | (unsigned long long)(unsigned int)i;
            if (pk < lmin) lmin = pk;
        }
    }
    atomicMin(&minpack, lmin);
    __syncthreads();

    find_digit(hist, TOPK_K, t, &s_digit, &s_need);
    const unsigned int d0 = s_digit;
    int need = s_need;                     // items to take inside bucket d0

    // Anchor = nearest fusion point (lowest index on key ties).
    const unsigned int amin = (unsigned int)(minpack & 0xFFFFFFFFull);
    const float q0x = fp[3 * amin + 0];
    const float q0y = fp[3 * amin + 1];
    const float q0z = fp[3 * amin + 2];

    // ---- Pass B: rescan. digit<d0 -> process now; digit==d0 -> compact.
    for (int i = t; i < n_fp; i += NTHREADS) {
        unsigned int k = compute_key(vx, vy, vz, fp, i);
        unsigned int d = k >> 24;
        if (d < d0) {
            process_point(i, fp, q0x, q0y, q0z, counts);
        } else if (d == d0) {
            unsigned int p = atomicAdd(&s_cand_count, 1u);
            if (p < CAND_CAP)
                cand[p] = ((unsigned long long)k << 32) |
                          (unsigned long long)(unsigned int)i;
        }
    }
    __syncthreads();
    const unsigned int nc = s_cand_count;

    if (nc <= CAND_CAP) {
        // ---- Main path: exact need-th smallest packed value among candidates
        // via 7x 8-bit radix passes over the (small) candidate list. Packed
        // (key, index) ordering reproduces top_k's lowest-index tie-break.
        unsigned long long prefix = (unsigned long long)d0 << 56;
        int needc = need;
        for (int pass = 0; pass < 7; ++pass) {
            const int shift = 48 - 8 * pass;
            hist[t] = 0;
            __syncthreads();
            const unsigned long long mask = ~0ull << (shift + 8);
            for (unsigned int j = t; j < nc; j += NTHREADS) {
                unsigned long long pk = cand[j];
                if ((pk & mask) == prefix)
                    atomicAdd(&hist[(unsigned int)(pk >> shift) & 255u], 1u);
            }
            __syncthreads();
            find_digit(hist, needc, t, &s_digit, &s_need);
            prefix |= (unsigned long long)s_digit << shift;
            needc = s_need;
        }
        const unsigned long long Pstar = prefix;  // exact cutoff (unique)
        for (unsigned int j = t; j < nc; j += NTHREADS) {
            unsigned long long pk = cand[j];
            if (pk <= Pstar)
                process_point((int)(unsigned int)(pk & 0xFFFFFFFFull),
                              fp, q0x, q0y, q0z, counts);
        }
        __syncthreads();
    } else {
        // ---- Fallback (statistically never): refine digits with full
        // rescans, then select with tie handling by index rank.
        unsigned int prefix = d0 << 24;
        int needf = need;
        for (int pass = 1; pass < 4; ++pass) {
            const int shift = 24 - 8 * pass;
            hist[t] = 0;
            __syncthreads();
            const unsigned int mask = 0xFFFFFFFFu << (shift + 8);
            for (int i = t; i < n_fp; i += NTHREADS) {
                unsigned int k = compute_key(vx, vy, vz, fp, i);
                if ((k & mask) == prefix)
                    atomicAdd(&hist[(k >> shift) & 255u], 1u);
            }
            __syncthreads();
            find_digit(hist, needf, t, &s_digit, &s_need);
            prefix |= s_digit << shift;
            needf = s_need;
        }
        const unsigned int V = prefix;
        if (t == 0) s_cand_count = 0;
        __syncthreads();
        for (int i = t; i < n_fp; i += NTHREADS) {
            unsigned int k = compute_key(vx, vy, vz, fp, i);
            if (k >= (d0 << 24)) {   // digit<d0 already processed in pass B
                if (k < V) {
                    process_point(i, fp, q0x, q0y, q0z, counts);
                } else if (k == V) {
                    unsigned int p = atomicAdd(&s_cand_count, 1u);
                    if (p < CAND_CAP)
                        cand[p] = (unsigned long long)(unsigned int)i;
                }
            }
        }
        __syncthreads();
        unsigned int ne = min(s_cand_count, (unsigned int)CAND_CAP);
        for (unsigned int j = t; j < ne; j += NTHREADS) {
            unsigned int my = (unsigned int)cand[j];
            int rank = 0;
            for (unsigned int l = 0; l < ne; ++l)
                rank += ((unsigned int)cand[l] < my) ? 1 : 0;
            if (rank < needf)
                process_point((int)my, fp, q0x, q0y, q0z, counts);
        }
        __syncthreads();
    }

    // ---- counts+1 -> L2-normalize*4 -> softmax (warp 0).
    if (t < 32) {
        float c = (float)counts[t] + 1.0f;
        float ss = c * c;
        #pragma unroll
        for (int o = 16; o > 0; o >>= 1) ss += __shfl_xor_sync(0xFFFFFFFFu, ss, o);
        float pip = (c / sqrtf(ss)) * 4.0f;
        float m = pip;
        #pragma unroll
        for (int o = 16; o > 0; o >>= 1)
            m = fmaxf(m, __shfl_xor_sync(0xFFFFFFFFu, m, o));
        float e = expf(pip - m);
        float se = e;
        #pragma unroll
        for (int o = 16; o > 0; o >>= 1) se += __shfl_xor_sync(0xFFFFFFFFu, se, o);
        out[b * PARTS + t] = e / se;
    }
}

extern "C" void kernel_launch(void* const* d_in, const int* in_sizes, int n_in,
                              void* d_out, int out_size)
{
    const float* vp = (const float*)d_in[0];   // sampled_vehicle_points (n_vp, 3)
    const float* fp = (const float*)d_in[1];   // fusion_point          (n_fp, 3)
    float* out = (float*)d_out;                // (n_vp, 32)

    const int n_vp = in_sizes[0] / 3;
    const int n_fp = in_sizes[1] / 3;

    scp_topk_bins_kernel<<<n_vp, NTHREADS>>>(vp, fp, out, n_fp);
}